// round 8
// baseline (speedup 1.0000x reference)
#include <cuda_runtime.h>

typedef unsigned long long u64;

#define B_  2
#define T_  2560
#define C_  768
#define H_  12
#define HD_ 64
#define M_  (B_*T_)   // 5120

// ---- scratch (static device arrays; no allocation) ----
__device__ float g_Q[B_*H_*T_*HD_];
__device__ float g_K[B_*H_*T_*HD_];
__device__ float g_V[B_*H_*T_*HD_];
__device__ float g_Y[B_*T_*C_];

// ---- packed f32x2 helpers (Blackwell FFMA2) ----
__device__ __forceinline__ u64 fma2(u64 a, u64 b, u64 c) {
    u64 d; asm("fma.rn.f32x2 %0, %1, %2, %3;" : "=l"(d) : "l"(a), "l"(b), "l"(c)); return d;
}
__device__ __forceinline__ u64 add2_(u64 a, u64 b) {
    u64 d; asm("add.rn.f32x2 %0, %1, %2;" : "=l"(d) : "l"(a), "l"(b)); return d;
}
__device__ __forceinline__ u64 pack2(float x, float y) {
    u64 d; asm("mov.b64 %0, {%1, %2};" : "=l"(d) : "f"(x), "f"(y)); return d;
}
__device__ __forceinline__ float2 unpack2(u64 v) {
    float2 r; asm("mov.b64 {%0, %1}, %2;" : "=f"(r.x), "=f"(r.y) : "l"(v)); return r;
}
__device__ __forceinline__ float ex2f_(float x) {
    float y; asm("ex2.approx.ftz.f32 %0, %1;" : "=f"(y) : "f"(x)); return y;
}

// ============================================================================
// GEMM: out[m,n] = sum_k A[m,k] * W[n,k] + bias[n]   (unchanged from R7: 379us)
// MODE 0: A = x, three outputs (z selects K/Q/V weights), out layout [B,H,T,hd]
// MODE 1: A = g_Y, out layout [M, C] (final projection into d_out)
// ============================================================================
#define TS_ 132   // smem row stride (floats)

template<int MODE>
__global__ void __launch_bounds__(256, 2) gemm_kernel(
    const float* __restrict__ A,
    const float* __restrict__ W0, const float* __restrict__ W1, const float* __restrict__ W2,
    const float* __restrict__ bias0, const float* __restrict__ bias1, const float* __restrict__ bias2,
    float* __restrict__ outp)
{
    __shared__ __align__(16) float As[16 * TS_];
    __shared__ __align__(16) float Bs[16 * TS_];

    const float* W; const float* bias; float* out;
    if (MODE == 0) {
        int z = blockIdx.z;
        W    = (z==0) ? W0    : ((z==1) ? W1    : W2);
        bias = (z==0) ? bias0 : ((z==1) ? bias1 : bias2);
        out  = (z==0) ? g_K   : ((z==1) ? g_Q   : g_V);
    } else {
        W = W0; bias = bias0; out = outp;
    }
    const float* Ap = (MODE == 0) ? A : (const float*)g_Y;

    int tid = threadIdx.x;
    int tx = tid & 15, ty = tid >> 4;
    int m0 = blockIdx.y * 128, n0 = blockIdx.x * 128;

    u64 acc[8][4];
    #pragma unroll
    for (int i = 0; i < 8; i++)
        #pragma unroll
        for (int j = 0; j < 4; j++) acc[i][j] = 0ull;

    int r0_ = tid >> 2,            c4_0 = tid & 3;
    int r1_ = (tid + 256) >> 2,    c4_1 = (tid + 256) & 3;

    float4 fA0, fA1, fW0, fW1;
    fA0 = *(const float4*)&Ap[(m0 + r0_) * C_ + c4_0 * 4];
    fW0 = *(const float4*)&W [(n0 + r0_) * C_ + c4_0 * 4];
    fA1 = *(const float4*)&Ap[(m0 + r1_) * C_ + c4_1 * 4];
    fW1 = *(const float4*)&W [(n0 + r1_) * C_ + c4_1 * 4];

    #pragma unroll 1
    for (int k0 = 0; k0 < C_; k0 += 16) {
        As[(c4_0*4+0)*TS_ + r0_] = fA0.x; As[(c4_0*4+1)*TS_ + r0_] = fA0.y;
        As[(c4_0*4+2)*TS_ + r0_] = fA0.z; As[(c4_0*4+3)*TS_ + r0_] = fA0.w;
        Bs[(c4_0*4+0)*TS_ + r0_] = fW0.x; Bs[(c4_0*4+1)*TS_ + r0_] = fW0.y;
        Bs[(c4_0*4+2)*TS_ + r0_] = fW0.z; Bs[(c4_0*4+3)*TS_ + r0_] = fW0.w;
        As[(c4_1*4+0)*TS_ + r1_] = fA1.x; As[(c4_1*4+1)*TS_ + r1_] = fA1.y;
        As[(c4_1*4+2)*TS_ + r1_] = fA1.z; As[(c4_1*4+3)*TS_ + r1_] = fA1.w;
        Bs[(c4_1*4+0)*TS_ + r1_] = fW1.x; Bs[(c4_1*4+1)*TS_ + r1_] = fW1.y;
        Bs[(c4_1*4+2)*TS_ + r1_] = fW1.z; Bs[(c4_1*4+3)*TS_ + r1_] = fW1.w;
        __syncthreads();

        if (k0 + 16 < C_) {
            fA0 = *(const float4*)&Ap[(m0 + r0_) * C_ + k0 + 16 + c4_0 * 4];
            fW0 = *(const float4*)&W [(n0 + r0_) * C_ + k0 + 16 + c4_0 * 4];
            fA1 = *(const float4*)&Ap[(m0 + r1_) * C_ + k0 + 16 + c4_1 * 4];
            fW1 = *(const float4*)&W [(n0 + r1_) * C_ + k0 + 16 + c4_1 * 4];
        }

        #pragma unroll
        for (int k = 0; k < 16; k++) {
            ulonglong2 b01 = *(const ulonglong2*)&Bs[k*TS_ + tx*8];
            ulonglong2 b23 = *(const ulonglong2*)&Bs[k*TS_ + tx*8 + 4];
            float4 a03 = *(const float4*)&As[k*TS_ + ty*8];
            float4 a47 = *(const float4*)&As[k*TS_ + ty*8 + 4];
            float av[8] = {a03.x, a03.y, a03.z, a03.w, a47.x, a47.y, a47.z, a47.w};
            #pragma unroll
            for (int i = 0; i < 8; i++) {
                u64 a2 = pack2(av[i], av[i]);
                acc[i][0] = fma2(a2, b01.x, acc[i][0]);
                acc[i][1] = fma2(a2, b01.y, acc[i][1]);
                acc[i][2] = fma2(a2, b23.x, acc[i][2]);
                acc[i][3] = fma2(a2, b23.y, acc[i][3]);
            }
        }
        __syncthreads();
    }

    int n_base = n0 + tx * 8;
    float4 bb0 = *(const float4*)&bias[n_base];
    float4 bb1 = *(const float4*)&bias[n_base + 4];
    #pragma unroll
    for (int i = 0; i < 8; i++) {
        int mm = m0 + ty*8 + i;
        float* p;
        if (MODE == 0) {
            int bi = mm / T_;
            int tq = mm - bi * T_;
            int h = n_base >> 6, d = n_base & 63;
            p = out + ((((bi * H_) + h) * T_ + tq) << 6) + d;   // [B,H,T,hd]
        } else {
            p = out + (size_t)mm * C_ + n_base;                 // [M,C]
        }
        float2 v0 = unpack2(acc[i][0]), v1 = unpack2(acc[i][1]);
        float2 v2 = unpack2(acc[i][2]), v3 = unpack2(acc[i][3]);
        *(float4*)p       = make_float4(v0.x + bb0.x, v0.y + bb0.y, v1.x + bb0.z, v1.y + bb0.w);
        *(float4*)(p + 4) = make_float4(v2.x + bb1.x, v2.y + bb1.y, v3.x + bb1.z, v3.y + bb1.w);
    }
}

// ============================================================================
// Attention (no-max softmax; mask (q%256) >= (k%256)), barrier-free.
// 128 threads/block = 32 quads. Quad owns mirror row pair {pl, 255-pl};
// quad lane qh = tid&3 owns dims [qh*16, qh*16+16).
// blockIdx.x = ti*4 + s, s in 0..3 selects pl range [32s, 32s+32).
// Work per quad = 257 keys (constant) -> perfectly balanced blocks, no smem,
// no __syncthreads; K/V rows LDG'd directly (warp-broadcast, L1-resident).
// Warp-uniform chunk bounds: 2-row chunks ci<=wboth, 1-row ci<=wlast.
// ============================================================================
template<int NR>
__device__ __forceinline__ void do_chunk(
    const float* __restrict__ Kt, const float* __restrict__ Vt,
    int ci, int qh, int rA, int rB,
    const u64 (&qA)[8], const u64 (&qB)[8],
    u64 (&aA)[8], u64 (&aB)[8], float& lA, float& lB)
{
    #pragma unroll
    for (int j0 = 0; j0 < 16; j0 += 8) {
        float pA[8], pB[8];
        #pragma unroll
        for (int j = 0; j < 8; j++) {
            const int kc = ci*16 + j0 + j;
            const ulonglong2* kr = (const ulonglong2*)(Kt + kc*64 + qh*16);
            u64 sA0 = 0ull, sA1 = 0ull, sB0 = 0ull, sB1 = 0ull;
            #pragma unroll
            for (int d = 0; d < 4; d++) {
                ulonglong2 kk = kr[d];
                if (NR == 2) {
                    sA0 = fma2(qA[2*d],   kk.x, sA0);
                    sA1 = fma2(qA[2*d+1], kk.y, sA1);
                }
                sB0 = fma2(qB[2*d],   kk.x, sB0);
                sB1 = fma2(qB[2*d+1], kk.y, sB1);
            }
            float sB; { float2 f = unpack2(add2_(sB0, sB1)); sB = f.x + f.y; }
            sB += __shfl_xor_sync(0xffffffffu, sB, 1);
            sB += __shfl_xor_sync(0xffffffffu, sB, 2);
            float pb = (rB >= kc) ? ex2f_(sB) : 0.f;
            pB[j] = pb; lB += pb;
            if (NR == 2) {
                float sA; { float2 f = unpack2(add2_(sA0, sA1)); sA = f.x + f.y; }
                sA += __shfl_xor_sync(0xffffffffu, sA, 1);
                sA += __shfl_xor_sync(0xffffffffu, sA, 2);
                float pa = (rA >= kc) ? ex2f_(sA) : 0.f;
                pA[j] = pa; lA += pa;
            }
        }
        #pragma unroll
        for (int j = 0; j < 8; j++) {
            const int kc = ci*16 + j0 + j;
            const ulonglong2* vr = (const ulonglong2*)(Vt + kc*64 + qh*16);
            u64 pB2 = pack2(pB[j], pB[j]);
            u64 pA2 = 0ull;
            if (NR == 2) pA2 = pack2(pA[j], pA[j]);
            #pragma unroll
            for (int d = 0; d < 4; d++) {
                ulonglong2 vv = vr[d];
                aB[2*d]   = fma2(pB2, vv.x, aB[2*d]);
                aB[2*d+1] = fma2(pB2, vv.y, aB[2*d+1]);
                if (NR == 2) {
                    aA[2*d]   = fma2(pA2, vv.x, aA[2*d]);
                    aA[2*d+1] = fma2(pA2, vv.y, aA[2*d+1]);
                }
            }
        }
    }
}

__global__ void __launch_bounds__(128, 3) attn_kernel()
{
    const int tid = threadIdx.x;
    const int bh  = blockIdx.y;            // b*12 + h
    const int ti  = blockIdx.x >> 2;       // tile 0..9
    const int s   = blockIdx.x & 3;        // pl quarter
    const int qh  = tid & 3;               // quad lane: dims [qh*16, qh*16+16)
    const int pl  = s*32 + (tid >> 2);     // 0..127
    const int w   = tid >> 5;              // warp 0..3
    const int rA  = pl;
    const int rB  = 255 - pl;
    const int wboth = (s*32 + (w<<3) + 7) >> 4;     // last chunk where A active in warp
    const int wlast = (255 - s*32 - (w<<3)) >> 4;   // last chunk where B active in warp

    const float* Qb = g_Q + (size_t)bh * T_ * HD_;
    const float* Kb = g_K + (size_t)bh * T_ * HD_;
    const float* Vb = g_V + (size_t)bh * T_ * HD_;

    const float SC = 0.125f * 1.4426950408889634f;  // (1/sqrt(64)) * log2(e)
    u64 qA[8], qB[8];
    {
        const float* pa = Qb + (ti*256 + rA) * HD_ + qh * 16;
        const float* pb = Qb + (ti*256 + rB) * HD_ + qh * 16;
        #pragma unroll
        for (int i = 0; i < 4; i++) {
            float4 v = *(const float4*)&pa[i*4];
            qA[2*i]   = pack2(v.x*SC, v.y*SC);
            qA[2*i+1] = pack2(v.z*SC, v.w*SC);
            float4 u = *(const float4*)&pb[i*4];
            qB[2*i]   = pack2(u.x*SC, u.y*SC);
            qB[2*i+1] = pack2(u.z*SC, u.w*SC);
        }
    }
    u64 aA[8], aB[8];
    #pragma unroll
    for (int i = 0; i < 8; i++) { aA[i] = 0ull; aB[i] = 0ull; }
    float lA = 0.f, lB = 0.f;

    #pragma unroll 1
    for (int kt = 0; kt < 10; kt++) {
        const float* Kt = Kb + kt * 256 * HD_;
        const float* Vt = Vb + kt * 256 * HD_;
        int ci = 0;
        #pragma unroll 1
        for (; ci <= wboth; ci++)
            do_chunk<2>(Kt, Vt, ci, qh, rA, rB, qA, qB, aA, aB, lA, lB);
        #pragma unroll 1
        for (; ci <= wlast; ci++)
            do_chunk<1>(Kt, Vt, ci, qh, rA, rB, qA, qB, aA, aB, lA, lB);
    }

    const float invA = 1.0f / lA;
    const float invB = 1.0f / lB;
    const int b = bh / H_, h = bh - (bh / H_) * H_;
    float* yA = g_Y + ((size_t)(b * T_ + ti*256 + rA)) * C_ + h * HD_ + qh * 16;
    float* yB = g_Y + ((size_t)(b * T_ + ti*256 + rB)) * C_ + h * HD_ + qh * 16;
    #pragma unroll
    for (int d = 0; d < 4; d++) {
        float2 v0 = unpack2(aA[2*d]), v1 = unpack2(aA[2*d+1]);
        *(float4*)&yA[d*4] = make_float4(v0.x*invA, v0.y*invA, v1.x*invA, v1.y*invA);
        float2 u0 = unpack2(aB[2*d]), u1 = unpack2(aB[2*d+1]);
        *(float4*)&yB[d*4] = make_float4(u0.x*invB, u0.y*invB, u1.x*invB, u1.y*invB);
    }
}

// ============================================================================
extern "C" void kernel_launch(void* const* d_in, const int* in_sizes, int n_in,
                              void* d_out, int out_size)
{
    (void)in_sizes; (void)n_in; (void)out_size;
    const float* x  = (const float*)d_in[0];
    const float* Wk = (const float*)d_in[1];
    const float* bk = (const float*)d_in[2];
    const float* Wq = (const float*)d_in[3];
    const float* bq = (const float*)d_in[4];
    const float* Wv = (const float*)d_in[5];
    const float* bv = (const float*)d_in[6];
    const float* Wp = (const float*)d_in[7];
    const float* bp = (const float*)d_in[8];
    float* out = (float*)d_out;

    gemm_kernel<0><<<dim3(C_/128, M_/128, 3), 256>>>(x, Wk, Wq, Wv, bk, bq, bv, nullptr);
    attn_kernel<<<dim3(40, B_*H_), 128>>>();
    gemm_kernel<1><<<dim3(C_/128, M_/128, 1), 256>>>(nullptr, Wp, Wp, Wp, bp, bp, bp, out);
}

// round 9
// speedup vs baseline: 1.9971x; 1.9971x over previous
#include <cuda_runtime.h>

typedef unsigned long long u64;

#define B_  2
#define T_  2560
#define C_  768
#define H_  12
#define HD_ 64
#define M_  (B_*T_)   // 5120

// ---- scratch (static device arrays; no allocation) ----
__device__ float g_Q[B_*H_*T_*HD_];
__device__ float g_K[B_*H_*T_*HD_];
__device__ float g_V[B_*H_*T_*HD_];
__device__ float g_Y[B_*T_*C_];

// ---- packed f32x2 helpers (Blackwell FFMA2) ----
__device__ __forceinline__ u64 fma2(u64 a, u64 b, u64 c) {
    u64 d; asm("fma.rn.f32x2 %0, %1, %2, %3;" : "=l"(d) : "l"(a), "l"(b), "l"(c)); return d;
}
__device__ __forceinline__ u64 pack2(float x, float y) {
    u64 d; asm("mov.b64 %0, {%1, %2};" : "=l"(d) : "f"(x), "f"(y)); return d;
}
__device__ __forceinline__ float2 unpack2(u64 v) {
    float2 r; asm("mov.b64 {%0, %1}, %2;" : "=f"(r.x), "=f"(r.y) : "l"(v)); return r;
}
__device__ __forceinline__ float ex2f_(float x) {
    float y; asm("ex2.approx.ftz.f32 %0, %1;" : "=f"(y) : "f"(x)); return y;
}

// ============================================================================
// GEMM: out[m,n] = sum_k A[m,k] * W[n,k] + bias[n]   (validated: 379us / 60% fma)
// MODE 0: A = x, three outputs (z selects K/Q/V weights), out layout [B,H,T,hd]
// MODE 1: A = g_Y, out layout [M, C] (final projection into d_out)
// ============================================================================
#define TS_ 132   // smem row stride (floats)

template<int MODE>
__global__ void __launch_bounds__(256, 2) gemm_kernel(
    const float* __restrict__ A,
    const float* __restrict__ W0, const float* __restrict__ W1, const float* __restrict__ W2,
    const float* __restrict__ bias0, const float* __restrict__ bias1, const float* __restrict__ bias2,
    float* __restrict__ outp)
{
    __shared__ __align__(16) float As[16 * TS_];
    __shared__ __align__(16) float Bs[16 * TS_];

    const float* W; const float* bias; float* out;
    if (MODE == 0) {
        int z = blockIdx.z;
        W    = (z==0) ? W0    : ((z==1) ? W1    : W2);
        bias = (z==0) ? bias0 : ((z==1) ? bias1 : bias2);
        out  = (z==0) ? g_K   : ((z==1) ? g_Q   : g_V);
    } else {
        W = W0; bias = bias0; out = outp;
    }
    const float* Ap = (MODE == 0) ? A : (const float*)g_Y;

    int tid = threadIdx.x;
    int tx = tid & 15, ty = tid >> 4;
    int m0 = blockIdx.y * 128, n0 = blockIdx.x * 128;

    u64 acc[8][4];
    #pragma unroll
    for (int i = 0; i < 8; i++)
        #pragma unroll
        for (int j = 0; j < 4; j++) acc[i][j] = 0ull;

    int r0_ = tid >> 2,            c4_0 = tid & 3;
    int r1_ = (tid + 256) >> 2,    c4_1 = (tid + 256) & 3;

    float4 fA0, fA1, fW0, fW1;
    fA0 = *(const float4*)&Ap[(m0 + r0_) * C_ + c4_0 * 4];
    fW0 = *(const float4*)&W [(n0 + r0_) * C_ + c4_0 * 4];
    fA1 = *(const float4*)&Ap[(m0 + r1_) * C_ + c4_1 * 4];
    fW1 = *(const float4*)&W [(n0 + r1_) * C_ + c4_1 * 4];

    #pragma unroll 1
    for (int k0 = 0; k0 < C_; k0 += 16) {
        As[(c4_0*4+0)*TS_ + r0_] = fA0.x; As[(c4_0*4+1)*TS_ + r0_] = fA0.y;
        As[(c4_0*4+2)*TS_ + r0_] = fA0.z; As[(c4_0*4+3)*TS_ + r0_] = fA0.w;
        Bs[(c4_0*4+0)*TS_ + r0_] = fW0.x; Bs[(c4_0*4+1)*TS_ + r0_] = fW0.y;
        Bs[(c4_0*4+2)*TS_ + r0_] = fW0.z; Bs[(c4_0*4+3)*TS_ + r0_] = fW0.w;
        As[(c4_1*4+0)*TS_ + r1_] = fA1.x; As[(c4_1*4+1)*TS_ + r1_] = fA1.y;
        As[(c4_1*4+2)*TS_ + r1_] = fA1.z; As[(c4_1*4+3)*TS_ + r1_] = fA1.w;
        Bs[(c4_1*4+0)*TS_ + r1_] = fW1.x; Bs[(c4_1*4+1)*TS_ + r1_] = fW1.y;
        Bs[(c4_1*4+2)*TS_ + r1_] = fW1.z; Bs[(c4_1*4+3)*TS_ + r1_] = fW1.w;
        __syncthreads();

        if (k0 + 16 < C_) {
            fA0 = *(const float4*)&Ap[(m0 + r0_) * C_ + k0 + 16 + c4_0 * 4];
            fW0 = *(const float4*)&W [(n0 + r0_) * C_ + k0 + 16 + c4_0 * 4];
            fA1 = *(const float4*)&Ap[(m0 + r1_) * C_ + k0 + 16 + c4_1 * 4];
            fW1 = *(const float4*)&W [(n0 + r1_) * C_ + k0 + 16 + c4_1 * 4];
        }

        #pragma unroll
        for (int k = 0; k < 16; k++) {
            ulonglong2 b01 = *(const ulonglong2*)&Bs[k*TS_ + tx*8];
            ulonglong2 b23 = *(const ulonglong2*)&Bs[k*TS_ + tx*8 + 4];
            float4 a03 = *(const float4*)&As[k*TS_ + ty*8];
            float4 a47 = *(const float4*)&As[k*TS_ + ty*8 + 4];
            float av[8] = {a03.x, a03.y, a03.z, a03.w, a47.x, a47.y, a47.z, a47.w};
            #pragma unroll
            for (int i = 0; i < 8; i++) {
                u64 a2 = pack2(av[i], av[i]);
                acc[i][0] = fma2(a2, b01.x, acc[i][0]);
                acc[i][1] = fma2(a2, b01.y, acc[i][1]);
                acc[i][2] = fma2(a2, b23.x, acc[i][2]);
                acc[i][3] = fma2(a2, b23.y, acc[i][3]);
            }
        }
        __syncthreads();
    }

    int n_base = n0 + tx * 8;
    float4 bb0 = *(const float4*)&bias[n_base];
    float4 bb1 = *(const float4*)&bias[n_base + 4];
    #pragma unroll
    for (int i = 0; i < 8; i++) {
        int mm = m0 + ty*8 + i;
        float* p;
        if (MODE == 0) {
            int bi = mm / T_;
            int tq = mm - bi * T_;
            int h = n_base >> 6, d = n_base & 63;
            p = out + ((((bi * H_) + h) * T_ + tq) << 6) + d;   // [B,H,T,hd]
        } else {
            p = out + (size_t)mm * C_ + n_base;                 // [M,C]
        }
        float2 v0 = unpack2(acc[i][0]), v1 = unpack2(acc[i][1]);
        float2 v2 = unpack2(acc[i][2]), v3 = unpack2(acc[i][3]);
        *(float4*)p       = make_float4(v0.x + bb0.x, v0.y + bb0.y, v1.x + bb0.z, v1.y + bb0.w);
        *(float4*)(p + 4) = make_float4(v2.x + bb1.x, v2.y + bb1.y, v3.x + bb1.z, v3.y + bb1.w);
    }
}

// ============================================================================
// GEMM-structured attention. Block = 64 query rows (tile ti, quarter j),
// 256 threads (tx 0..15 = 4 key/dim cols, ty 0..15 = 4 query rows).
// Per key tile: j+1 chunks of 64 keys; only the c0==r0 chunk is masked.
// Chunk: [K/V gmem->smem] QK^T 64x64x64 GEMM -> softmax(ex2, no max) ->
// S^T -> smem -> AV 64x64x64 GEMM into persistent O accumulator.
// Smem tiles k-major, stride 68. No-max softmax (scores |s|<~8, safe).
// ============================================================================
#define AS_ 68   // attn smem stride (floats), %4==0 for float4 rows

__global__ void __launch_bounds__(256, 2) attn_kernel()
{
    extern __shared__ __align__(16) float sm[];
    float* Qs = sm;                 // [64][AS_]  Qs[d][q]
    float* Ks = sm + 64*AS_;        // [64][AS_]  Ks[d][k]
    float* Vs = sm + 2*64*AS_;      // [64][AS_]  Vs[k][dd]
    float* Ss = sm + 3*64*AS_;      // [64][AS_]  Ss[k][q]

    const int tid = threadIdx.x;
    const int tx  = tid & 15;       // key / out-dim columns tx*4..+3
    const int ty  = tid >> 4;       // query rows ty*4..+3
    const int tx4 = tx * 4, ty4 = ty * 4;

    const int bh = blockIdx.y;                 // b*12 + h
    const int qb = blockIdx.x;                 // 0..39
    const int ti = qb >> 2;                    // tile 0..9
    const int j  = 3 - (qb & 3);               // row quarter, heavy-first
    const int r0 = j * 64;                     // base row within tile

    const float* Qb = g_Q + (size_t)bh * T_ * HD_;
    const float* Kb = g_K + (size_t)bh * T_ * HD_;
    const float* Vb = g_V + (size_t)bh * T_ * HD_;

    // ---- load Q tile (64 rows x 64 dims), scaled, transposed to Qs[d][q] ----
    const float SC = 0.125f * 1.4426950408889634f;  // (1/sqrt(64)) * log2(e)
    {
        const float4* Qsrc = (const float4*)(Qb + (size_t)(ti*256 + r0) * HD_);
        #pragma unroll
        for (int i = 0; i < 4; i++) {
            int id = tid + i * 256;          // 0..1023
            int row = id >> 4, c4 = id & 15;
            float4 q = Qsrc[row*16 + c4];
            Qs[(c4*4+0)*AS_ + row] = q.x * SC;
            Qs[(c4*4+1)*AS_ + row] = q.y * SC;
            Qs[(c4*4+2)*AS_ + row] = q.z * SC;
            Qs[(c4*4+3)*AS_ + row] = q.w * SC;
        }
    }

    u64   oacc[4][2];                 // O[qi][dd pairs]
    float lrow[4] = {0.f, 0.f, 0.f, 0.f};
    #pragma unroll
    for (int qi = 0; qi < 4; qi++) { oacc[qi][0] = 0ull; oacc[qi][1] = 0ull; }

    __syncthreads();   // Qs ready (also serves as first "smem free")

    #pragma unroll 1
    for (int kt = 0; kt < 10; kt++) {
        #pragma unroll 1
        for (int cj = 0; cj <= j; cj++) {
            const bool diag = (cj == j);
            // ---- load K,V chunk (64 keys x 64 dims) ----
            {
                const float4* Ksrc = (const float4*)(Kb + (size_t)(kt*256 + cj*64) * HD_);
                const float4* Vsrc = (const float4*)(Vb + (size_t)(kt*256 + cj*64) * HD_);
                #pragma unroll
                for (int i = 0; i < 4; i++) {
                    int id = tid + i * 256;
                    int row = id >> 4, c4 = id & 15;
                    float4 k = Ksrc[row*16 + c4];
                    Ks[(c4*4+0)*AS_ + row] = k.x;
                    Ks[(c4*4+1)*AS_ + row] = k.y;
                    Ks[(c4*4+2)*AS_ + row] = k.z;
                    Ks[(c4*4+3)*AS_ + row] = k.w;
                    float4 v = Vsrc[row*16 + c4];
                    *(float4*)&Vs[row*AS_ + c4*4] = v;
                }
            }
            __syncthreads();   // K/V ready

            // ---- QK^T: s[qi][ki] = sum_d Q[q][d] K[k][d] ----
            u64 sacc[4][2];
            #pragma unroll
            for (int qi = 0; qi < 4; qi++) { sacc[qi][0] = 0ull; sacc[qi][1] = 0ull; }
            #pragma unroll 8
            for (int d = 0; d < 64; d++) {
                float4 a = *(const float4*)&Qs[d*AS_ + ty4];
                ulonglong2 b = *(const ulonglong2*)&Ks[d*AS_ + tx4];
                float av[4] = {a.x, a.y, a.z, a.w};
                #pragma unroll
                for (int qi = 0; qi < 4; qi++) {
                    u64 a2 = pack2(av[qi], av[qi]);
                    sacc[qi][0] = fma2(a2, b.x, sacc[qi][0]);
                    sacc[qi][1] = fma2(a2, b.y, sacc[qi][1]);
                }
            }

            // ---- softmax (no max) + transpose-store S ----
            float p[4][4];
            #pragma unroll
            for (int qi = 0; qi < 4; qi++) {
                float2 f0 = unpack2(sacc[qi][0]);
                float2 f1 = unpack2(sacc[qi][1]);
                float sv[4] = {f0.x, f0.y, f1.x, f1.y};
                #pragma unroll
                for (int ki = 0; ki < 4; ki++) {
                    float pv;
                    if (diag) pv = (ty4 + qi >= tx4 + ki) ? ex2f_(sv[ki]) : 0.f;
                    else      pv = ex2f_(sv[ki]);
                    p[qi][ki] = pv;
                    lrow[qi] += pv;
                }
            }
            #pragma unroll
            for (int ki = 0; ki < 4; ki++)
                *(float4*)&Ss[(tx4+ki)*AS_ + ty4] =
                    make_float4(p[0][ki], p[1][ki], p[2][ki], p[3][ki]);
            __syncthreads();   // S ready

            // ---- AV: O[qi][dd] += S[q][k] V[k][dd] ----
            #pragma unroll 8
            for (int k = 0; k < 64; k++) {
                float4 a = *(const float4*)&Ss[k*AS_ + ty4];
                ulonglong2 v = *(const ulonglong2*)&Vs[k*AS_ + tx4];
                float av[4] = {a.x, a.y, a.z, a.w};
                #pragma unroll
                for (int qi = 0; qi < 4; qi++) {
                    u64 a2 = pack2(av[qi], av[qi]);
                    oacc[qi][0] = fma2(a2, v.x, oacc[qi][0]);
                    oacc[qi][1] = fma2(a2, v.y, oacc[qi][1]);
                }
            }
            __syncthreads();   // smem free for next chunk
        }
    }

    // ---- finalize: reduce l across tx (lane bits 0..3), write O ----
    #pragma unroll
    for (int qi = 0; qi < 4; qi++) {
        float l = lrow[qi];
        l += __shfl_xor_sync(0xffffffffu, l, 1);
        l += __shfl_xor_sync(0xffffffffu, l, 2);
        l += __shfl_xor_sync(0xffffffffu, l, 4);
        l += __shfl_xor_sync(0xffffffffu, l, 8);
        lrow[qi] = 1.0f / l;
    }
    const int b = bh / H_, h = bh - (bh / H_) * H_;
    #pragma unroll
    for (int qi = 0; qi < 4; qi++) {
        int tg = ti*256 + r0 + ty4 + qi;                       // token row
        float* yp = g_Y + ((size_t)(b * T_ + tg)) * C_ + h * HD_ + tx4;
        float2 v0 = unpack2(oacc[qi][0]);
        float2 v1 = unpack2(oacc[qi][1]);
        float inv = lrow[qi];
        *(float4*)yp = make_float4(v0.x*inv, v0.y*inv, v1.x*inv, v1.y*inv);
    }
}

// ============================================================================
extern "C" void kernel_launch(void* const* d_in, const int* in_sizes, int n_in,
                              void* d_out, int out_size)
{
    (void)in_sizes; (void)n_in; (void)out_size;
    const float* x  = (const float*)d_in[0];
    const float* Wk = (const float*)d_in[1];
    const float* bk = (const float*)d_in[2];
    const float* Wq = (const float*)d_in[3];
    const float* bq = (const float*)d_in[4];
    const float* Wv = (const float*)d_in[5];
    const float* bv = (const float*)d_in[6];
    const float* Wp = (const float*)d_in[7];
    const float* bp = (const float*)d_in[8];
    float* out = (float*)d_out;

    const int attn_smem = 4 * 64 * AS_ * sizeof(float);   // 69632 B
    cudaFuncSetAttribute(attn_kernel, cudaFuncAttributeMaxDynamicSharedMemorySize, attn_smem);

    gemm_kernel<0><<<dim3(C_/128, M_/128, 3), 256>>>(x, Wk, Wq, Wv, bk, bq, bv, nullptr);
    attn_kernel<<<dim3(40, B_*H_), 256, attn_smem>>>();
    gemm_kernel<1><<<dim3(C_/128, M_/128, 1), 256>>>(nullptr, Wp, Wp, Wp, bp, bp, bp, out);
}